// round 8
// baseline (speedup 1.0000x reference)
#include <cuda_runtime.h>
#include <cuda_fp16.h>
#include <math.h>
#include <stdint.h>

// ===========================================================================
// DivFreeNetwork, forward-mode (primal + 4 tangents = 5 rows/point).
// GEMMs via mma.sync fp16 hi/lo split (3 products), fp32 accumulate.
// R8: R7 fusion fixed — ping-pong activation buffers (no aliasing), two-pass
//     40-row epilogue staging (no smem overflow). 80x64 tile, 3 CTAs/SM.
// acc[2j]   covers cols j*16 + 0..7   (b regs {0,2})
// acc[2j+1] covers cols j*16 + 8..15  (b regs {1,3})
// ===========================================================================

#define DM 1024
#define ODIM 448
#define NLAY 4
#define MAXB 65536
#define MROWS (MAXB * 5)

__device__ __half g_A0h[(size_t)MROWS * DM];
__device__ __half g_A0l[(size_t)MROWS * DM];
__device__ __half g_A1h[(size_t)MROWS * DM];
__device__ __half g_A1l[(size_t)MROWS * DM];
__device__ float  g_OUT[(size_t)MROWS * ODIM];
__device__ __half g_WThi[(size_t)NLAY * DM * DM + 512 * DM];
__device__ __half g_WTlo[(size_t)NLAY * DM * DM + 512 * DM];

__device__ __forceinline__ uint32_t smem_u32(const void* p) {
    uint32_t a;
    asm("{ .reg .u64 t; cvta.to.shared.u64 t, %1; cvt.u32.u64 %0, t; }" : "=r"(a) : "l"(p));
    return a;
}
#define SWZ(o) ((o) ^ (((o) >> 3) & 0x70))

__device__ __forceinline__ void cp16(uint32_t so, const void* g) {
    asm volatile("cp.async.cg.shared.global [%0], [%1], 16;" :: "r"(so), "l"(g));
}
__device__ __forceinline__ void ldsm4(uint32_t* r, uint32_t addr) {
    asm volatile("ldmatrix.sync.aligned.m8n8.x4.shared.b16 {%0,%1,%2,%3}, [%4];"
                 : "=r"(r[0]), "=r"(r[1]), "=r"(r[2]), "=r"(r[3]) : "r"(addr));
}
__device__ __forceinline__ void mma16816(float* c, const uint32_t* a, uint32_t b0, uint32_t b1) {
    asm volatile("mma.sync.aligned.m16n8k16.row.col.f32.f16.f16.f32 "
                 "{%0,%1,%2,%3}, {%4,%5,%6,%7}, {%8,%9}, {%0,%1,%2,%3};"
                 : "+f"(c[0]), "+f"(c[1]), "+f"(c[2]), "+f"(c[3])
                 : "r"(a[0]), "r"(a[1]), "r"(a[2]), "r"(a[3]), "r"(b0), "r"(b1));
}

__device__ __forceinline__ float sigf(float p) { return 1.0f / (1.0f + expf(-p)); }

__device__ __forceinline__ void store4split(__half* ph, __half* pl, float4 v) {
    __align__(8) __half h[4], l[4];
    float vv[4] = {v.x, v.y, v.z, v.w};
#pragma unroll
    for (int i = 0; i < 4; i++) {
        h[i] = __float2half(vv[i]);
        l[i] = __float2half(vv[i] - __half2float(h[i]));
    }
    *(uint2*)ph = *(uint2*)h;
    *(uint2*)pl = *(uint2*)l;
}

// ------------------ prep: transpose + hi/lo split of weights ----------------
__global__ void prep_transpose(const float* __restrict__ W,
                               __half* __restrict__ Thi,
                               __half* __restrict__ Tlo,
                               int Krows, int Ncols)
{
    __shared__ float t[32][33];
    const float* Wz = W + (size_t)blockIdx.z * Krows * Ncols;
    __half* Hz = Thi + (size_t)blockIdx.z * Ncols * Krows;
    __half* Lz = Tlo + (size_t)blockIdx.z * Ncols * Krows;
    int n0 = blockIdx.x * 32, k0 = blockIdx.y * 32;
    int tx = threadIdx.x, ty = threadIdx.y;
#pragma unroll
    for (int i = 0; i < 4; i++)
        t[ty + 8 * i][tx] = Wz[(size_t)(k0 + ty + 8 * i) * Ncols + n0 + tx];
    __syncthreads();
#pragma unroll
    for (int i = 0; i < 4; i++) {
        int n = n0 + ty + 8 * i;
        float v = t[tx][ty + 8 * i];
        __half h = __float2half(v);
        Hz[(size_t)n * Krows + k0 + tx] = h;
        Lz[(size_t)n * Krows + k0 + tx] = __float2half(v - __half2float(h));
    }
}

// ---------------- layer 0: fused input GEMV + activation -------------------
__global__ void layer0_kernel(const float* __restrict__ x,
                              const float* __restrict__ W0,
                              const float* __restrict__ b0,
                              __half* __restrict__ Ah,
                              __half* __restrict__ Al, int B)
{
    int idx = blockIdx.x * blockDim.x + threadIdx.x;
    if (idx >= B * 256) return;
    int b = idx >> 8;
    int c = (idx & 255) * 4;
    float x0 = __ldg(x + b * 4 + 0), x1 = __ldg(x + b * 4 + 1);
    float x2 = __ldg(x + b * 4 + 2), x3 = __ldg(x + b * 4 + 3);
    float4 w0 = *(const float4*)(W0 + c);
    float4 w1 = *(const float4*)(W0 + 1024 + c);
    float4 w2 = *(const float4*)(W0 + 2048 + c);
    float4 w3 = *(const float4*)(W0 + 3072 + c);
    float4 bb = *(const float4*)(b0 + c);
    float p[4], act[4], d[4];
    float wv[4][4] = {{w0.x, w1.x, w2.x, w3.x}, {w0.y, w1.y, w2.y, w3.y},
                      {w0.z, w1.z, w2.z, w3.z}, {w0.w, w1.w, w2.w, w3.w}};
    float bv[4] = {bb.x, bb.y, bb.z, bb.w};
#pragma unroll
    for (int i = 0; i < 4; i++) {
        p[i] = fmaf(x0, wv[i][0], fmaf(x1, wv[i][1], fmaf(x2, wv[i][2], fmaf(x3, wv[i][3], bv[i]))));
        float sg = sigf(p[i]);
        act[i] = p[i] * sg;
        d[i] = sg * fmaf(p[i], 1.0f - sg, 1.0f);
    }
    size_t base = (size_t)b * (5 * DM) + c;
    store4split(Ah + base, Al + base, make_float4(act[0], act[1], act[2], act[3]));
#pragma unroll
    for (int j = 0; j < 4; j++) {
        float4 t = make_float4(d[0] * wv[0][j], d[1] * wv[1][j], d[2] * wv[2][j], d[3] * wv[3][j]);
        store4split(Ah + base + (j + 1) * DM, Al + base + (j + 1) * DM, t);
    }
}

// ---------------- fused HMMA GEMM + activation epilogue --------------------
#define STG 36864
#define EPAD 65

__device__ __forceinline__ void load_stage(uint32_t sb,
    const __half* Ah, const __half* Al, const __half* Bh, const __half* Bl,
    int row0, int col0, int k0, int K, int tid)
{
#pragma unroll
    for (int pl = 0; pl < 2; pl++) {           // A planes: 80 rows
        const __half* g = pl ? Al : Ah;
        uint32_t pb = sb + pl * 10240u;
#pragma unroll
        for (int it = 0; it < 4; it++) {
            int t = tid + it * 160;
            int r = t >> 3, cc = t & 7;
            cp16(pb + SWZ(r * 128 + cc * 16), g + (size_t)(row0 + r) * K + k0 + cc * 8);
        }
    }
#pragma unroll
    for (int pl = 0; pl < 2; pl++) {           // B planes: 64 rows
        const __half* g = pl ? Bl : Bh;
        uint32_t pb = sb + 20480u + pl * 8192u;
#pragma unroll
        for (int it = 0; it < 4; it++) {
            int t = tid + it * 160;
            if (t < 512) {
                int r = t >> 3, cc = t & 7;
                cp16(pb + SWZ(r * 128 + cc * 16), g + (size_t)(col0 + r) * K + k0 + cc * 8);
            }
        }
    }
    asm volatile("cp.async.commit_group;" ::: "memory");
}

__global__ void __launch_bounds__(160, 3)
gemm_fused(const __half* __restrict__ Ain, const __half* __restrict__ Alin,
           const __half* __restrict__ Bh, const __half* __restrict__ Bl,
           const float* __restrict__ bias,
           __half* __restrict__ AhOut, __half* __restrict__ AlOut,
           float* __restrict__ C,
           int K, int ldc, int Nstore, int mode)
{
    extern __shared__ char smem[];
    uint32_t sbase = smem_u32(smem);
    int tid = threadIdx.x, wid = tid >> 5, lid = tid & 31;
    int row0 = blockIdx.y * 80;
    int col0 = blockIdx.x * 64;

    float acc[8][4];
#pragma unroll
    for (int j = 0; j < 8; j++)
#pragma unroll
        for (int q = 0; q < 4; q++) acc[j][q] = 0.0f;

    const int KITER = K >> 6;
    load_stage(sbase + 0 * STG, Ain, Alin, Bh, Bl, row0, col0, 0, K, tid);
    load_stage(sbase + 1 * STG, Ain, Alin, Bh, Bl, row0, col0, 64, K, tid);

    int lrow = lid & 15;
    int kadd = (lid & 16) ? 8 : 0;

    for (int i = 0; i < KITER; i++) {
        asm volatile("cp.async.wait_group 1;" ::: "memory");
        __syncthreads();
        uint32_t stg = sbase + (i & 1) * STG;
        uint32_t Abh = stg, Abl = stg + 10240, Bbh = stg + 20480, Bbl = stg + 28672;

#pragma unroll
        for (int ks = 0; ks < 4; ks++) {
            int col = ks * 16 + kadd;
            uint32_t ahi[4], alo[4], bhi[4][4], blo[4][4];
            {
                uint32_t off = SWZ((wid * 16 + lrow) * 128 + col * 2);
                ldsm4(ahi, Abh + off);
                ldsm4(alo, Abl + off);
            }
#pragma unroll
            for (int j = 0; j < 4; j++) {
                uint32_t off = SWZ((j * 16 + lrow) * 128 + col * 2);
                ldsm4(bhi[j], Bbh + off);
                ldsm4(blo[j], Bbl + off);
            }
#pragma unroll
            for (int j = 0; j < 4; j++) {
                mma16816(acc[2 * j],     ahi, bhi[j][0], bhi[j][2]);
                mma16816(acc[2 * j + 1], ahi, bhi[j][1], bhi[j][3]);
            }
#pragma unroll
            for (int j = 0; j < 4; j++) {
                mma16816(acc[2 * j],     ahi, blo[j][0], blo[j][2]);
                mma16816(acc[2 * j + 1], ahi, blo[j][1], blo[j][3]);
            }
#pragma unroll
            for (int j = 0; j < 4; j++) {
                mma16816(acc[2 * j],     alo, bhi[j][0], bhi[j][2]);
                mma16816(acc[2 * j + 1], alo, bhi[j][1], bhi[j][3]);
            }
        }
        __syncthreads();
        if (i + 2 < KITER)
            load_stage(stg, Ain, Alin, Bh, Bl, row0, col0, (i + 2) * 64, K, tid);
        else
            asm volatile("cp.async.commit_group;" ::: "memory");
    }

    int trow = lid >> 2, tcol = (lid & 3) * 2;

    if (mode == 1) {
#pragma unroll
        for (int j = 0; j < 4; j++) {
#pragma unroll
            for (int h = 0; h < 2; h++) {
                int gc = col0 + j * 16 + h * 8 + tcol;
                if (gc >= Nstore) continue;
                const float* a = acc[2 * j + h];
                int gr0 = row0 + wid * 16 + trow;
                float2 v0 = make_float2(a[0], a[1]);
                float2 v1 = make_float2(a[2], a[3]);
                if (gr0 % 5 == 0)       { v0.x += bias[gc]; v0.y += bias[gc + 1]; }
                if ((gr0 + 8) % 5 == 0) { v1.x += bias[gc]; v1.y += bias[gc + 1]; }
                *(float2*)(C + (size_t)gr0 * ldc + gc) = v0;
                *(float2*)(C + (size_t)(gr0 + 8) * ldc + gc) = v1;
            }
        }
        return;
    }

    // ---- mode 0: two-pass staging (40 rows = 8 points each) + transform ----
    float* sf = (float*)smem;
#pragma unroll
    for (int pass = 0; pass < 2; pass++) {
        int rlo = pass * 40, rhi = rlo + 40;
        __syncthreads();   // previous use of smem done (MMA reads / prior pass)
#pragma unroll
        for (int j = 0; j < 4; j++) {
#pragma unroll
            for (int h = 0; h < 2; h++) {
                int c = j * 16 + h * 8 + tcol;
                int r1 = wid * 16 + trow;
                int r2 = r1 + 8;
                const float* a = acc[2 * j + h];
                if (r1 >= rlo && r1 < rhi) {
                    sf[(r1 - rlo) * EPAD + c] = a[0];
                    sf[(r1 - rlo) * EPAD + c + 1] = a[1];
                }
                if (r2 >= rlo && r2 < rhi) {
                    sf[(r2 - rlo) * EPAD + c] = a[2];
                    sf[(r2 - rlo) * EPAD + c + 1] = a[3];
                }
            }
        }
        __syncthreads();

        // 8 points x 16 col-groups(4 cols) = 128 tasks
        for (int q = tid; q < 128; q += 160) {
            int ptl = q >> 4;                 // 0..7
            int c = (q & 15) * 4;
            int r = ptl * 5;                  // local row within this 40-row pass
            float4 bb = *(const float4*)(bias + col0 + c);
            float bv[4] = {bb.x, bb.y, bb.z, bb.w};
            float av[4], dv[4];
#pragma unroll
            for (int u = 0; u < 4; u++) {
                float p = sf[r * EPAD + c + u] + bv[u];
                float sg = sigf(p);
                av[u] = p * sg;
                dv[u] = sg * fmaf(p, 1.0f - sg, 1.0f);
            }
            int gpt = (row0 / 5) + pass * 8 + ptl;
            size_t base = (size_t)gpt * (5 * DM) + col0 + c;
            store4split(AhOut + base, AlOut + base, make_float4(av[0], av[1], av[2], av[3]));
#pragma unroll
            for (int j = 1; j < 5; j++) {
                float4 t;
                t.x = sf[(r + j) * EPAD + c + 0] * dv[0];
                t.y = sf[(r + j) * EPAD + c + 1] * dv[1];
                t.z = sf[(r + j) * EPAD + c + 2] * dv[2];
                t.w = sf[(r + j) * EPAD + c + 3] * dv[3];
                store4split(AhOut + base + j * DM, AlOut + base + j * DM, t);
            }
        }
    }
}

// ---------------- head: softmax-mixture derivative, warp per point ---------
__global__ void finalize_kernel(const float* __restrict__ OUT,
                                float* __restrict__ y, int B)
{
    int warp = (blockIdx.x * blockDim.x + threadIdx.x) >> 5;
    int lane = threadIdx.x & 31;
    if (warp >= B) return;
    const float* o = OUT + (size_t)warp * 5 * ODIM;

    float l0 = o[lane], l1 = o[lane + 32];
    float m = fmaxf(l0, l1);
#pragma unroll
    for (int s = 16; s; s >>= 1) m = fmaxf(m, __shfl_xor_sync(0xFFFFFFFFu, m, s));
    float e0 = expf(l0 - m), e1 = expf(l1 - m);
    float S = e0 + e1;
#pragma unroll
    for (int s = 16; s; s >>= 1) S += __shfl_xor_sync(0xFFFFFFFFu, S, s);
    float s0 = e0 / S, s1 = e1 / S;

    float v0[6], v1[6];
#pragma unroll
    for (int t = 0; t < 6; t++) {
        v0[t] = o[64 + 6 * lane + t];
        v1[t] = o[64 + 6 * (lane + 32) + t];
    }

    float Dm[4][6];
#pragma unroll
    for (int j = 0; j < 4; j++) {
        const float* tj = o + (size_t)(j + 1) * ODIM;
        float g0 = tj[lane], g1 = tj[lane + 32];
        float dot = s0 * g0 + s1 * g1;
#pragma unroll
        for (int s = 16; s; s >>= 1) dot += __shfl_xor_sync(0xFFFFFFFFu, dot, s);
#pragma unroll
        for (int t = 0; t < 6; t++) {
            float dv0 = tj[64 + 6 * lane + t];
            float dv1 = tj[64 + 6 * (lane + 32) + t];
            float val = s0 * fmaf(g0 - dot, v0[t], dv0) + s1 * fmaf(g1 - dot, v1[t], dv1);
#pragma unroll
            for (int s = 16; s; s >>= 1) val += __shfl_xor_sync(0xFFFFFFFFu, val, s);
            Dm[j][t] = val;
        }
    }
    if (lane == 0) {
        float u0 =  Dm[1][0] + Dm[2][1] + Dm[3][2];
        float u1 = -Dm[0][0] + Dm[2][3] + Dm[3][4];
        float u2 = -Dm[0][1] - Dm[1][3] + Dm[3][5];
        float u3 = -Dm[0][2] - Dm[1][4] - Dm[2][5];
        *(float4*)(y + (size_t)warp * 4) = make_float4(u0 * 10.0f, u1, u2, u3);
    }
}

// ---------------------------------------------------------------------------
extern "C" void kernel_launch(void* const* d_in, const int* in_sizes, int n_in,
                              void* d_out, int out_size)
{
    const float* x    = (const float*)d_in[0];
    const float* W0   = (const float*)d_in[1];
    const float* b0   = (const float*)d_in[2];
    const float* Wh   = (const float*)d_in[3];
    const float* bh   = (const float*)d_in[4];
    const float* Wout = (const float*)d_in[5];
    const float* bout = (const float*)d_in[6];
    float* y = (float*)d_out;

    int B = in_sizes[0] / 4;
    int M = B * 5;

    __half *A0h, *A0l, *A1h, *A1l, *WThi, *WTlo;
    float *OUTB;
    cudaGetSymbolAddress((void**)&A0h, g_A0h);
    cudaGetSymbolAddress((void**)&A0l, g_A0l);
    cudaGetSymbolAddress((void**)&A1h, g_A1h);
    cudaGetSymbolAddress((void**)&A1l, g_A1l);
    cudaGetSymbolAddress((void**)&OUTB, g_OUT);
    cudaGetSymbolAddress((void**)&WThi, g_WThi);
    cudaGetSymbolAddress((void**)&WTlo, g_WTlo);

    static int smem_set = 0;
    if (!smem_set) {
        cudaFuncSetAttribute(gemm_fused, cudaFuncAttributeMaxDynamicSharedMemorySize,
                             2 * STG);
        smem_set = 1;
    }

    prep_transpose<<<dim3(32, 32, NLAY), dim3(32, 8)>>>(Wh, WThi, WTlo, DM, DM);
    prep_transpose<<<dim3(ODIM / 32, 32, 1), dim3(32, 8)>>>(
        Wout, WThi + (size_t)NLAY * DM * DM, WTlo + (size_t)NLAY * DM * DM, DM, ODIM);

    layer0_kernel<<<(B * 256 + 255) / 256, 256>>>(x, W0, b0, A0h, A0l, B);

    // ping-pong: layer l reads cur, writes nxt
    __half* curh = A0h; __half* curl = A0l;
    __half* nxth = A1h; __half* nxtl = A1l;
    dim3 gH(DM / 64, M / 80);
    for (int l = 0; l < NLAY; l++) {
        gemm_fused<<<gH, 160, 2 * STG>>>(curh, curl,
            WThi + (size_t)l * DM * DM, WTlo + (size_t)l * DM * DM,
            bh + (size_t)l * DM, nxth, nxtl, nullptr, DM, DM, DM, 0);
        __half* th = curh; __half* tl = curl;
        curh = nxth; curl = nxtl; nxth = th; nxtl = tl;
    }

    dim3 gO(512 / 64, M / 80);
    gemm_fused<<<gO, 160, 2 * STG>>>(curh, curl,
        WThi + (size_t)NLAY * DM * DM, WTlo + (size_t)NLAY * DM * DM,
        bout, nullptr, nullptr, OUTB, DM, ODIM, ODIM, 1);

    finalize_kernel<<<(B * 32 + 255) / 256, 256>>>(OUTB, y, B);
}

// round 9
// speedup vs baseline: 1.1621x; 1.1621x over previous
#include <cuda_runtime.h>
#include <cuda_fp16.h>
#include <math.h>
#include <stdint.h>

// ===========================================================================
// DivFreeNetwork, forward-mode. Primal (B x 1024) and tangent (4B x 1024)
// matrices kept SEPARATE so the GEMM epilogue is element-local:
//   primal  : act = silu(acc+bias), also store d = silu'(p) to D
//   tangent : act = d * acc   (d read from D, row/col local)
// GEMM core = R6 winner: 128x64 CTA, 256 thr, warp 32x32, 2 CTAs/SM,
// fp16 hi/lo split (3 products), product-major MMA order.
// ===========================================================================

#define DM 1024
#define ODIM 448
#define NLAY 4
#define MAXB 65536
#define TROWS (4 * MAXB)

__device__ __half g_P0h[(size_t)MAXB * DM];
__device__ __half g_P0l[(size_t)MAXB * DM];
__device__ __half g_P1h[(size_t)MAXB * DM];
__device__ __half g_P1l[(size_t)MAXB * DM];
__device__ __half g_T0h[(size_t)TROWS * DM];
__device__ __half g_T0l[(size_t)TROWS * DM];
__device__ __half g_T1h[(size_t)TROWS * DM];
__device__ __half g_T1l[(size_t)TROWS * DM];
__device__ float  g_D[(size_t)MAXB * DM];
__device__ float  g_OUTP[(size_t)MAXB * ODIM];
__device__ float  g_OUTT[(size_t)TROWS * ODIM];
__device__ __half g_WThi[(size_t)NLAY * DM * DM + 512 * DM];
__device__ __half g_WTlo[(size_t)NLAY * DM * DM + 512 * DM];

__device__ __forceinline__ uint32_t smem_u32(const void* p) {
    uint32_t a;
    asm("{ .reg .u64 t; cvta.to.shared.u64 t, %1; cvt.u32.u64 %0, t; }" : "=r"(a) : "l"(p));
    return a;
}
#define SWZ(o) ((o) ^ (((o) >> 3) & 0x70))

__device__ __forceinline__ void cp16(uint32_t so, const void* g) {
    asm volatile("cp.async.cg.shared.global [%0], [%1], 16;" :: "r"(so), "l"(g));
}
__device__ __forceinline__ void ldsm4(uint32_t* r, uint32_t addr) {
    asm volatile("ldmatrix.sync.aligned.m8n8.x4.shared.b16 {%0,%1,%2,%3}, [%4];"
                 : "=r"(r[0]), "=r"(r[1]), "=r"(r[2]), "=r"(r[3]) : "r"(addr));
}
__device__ __forceinline__ void mma16816(float* c, const uint32_t* a, uint32_t b0, uint32_t b1) {
    asm volatile("mma.sync.aligned.m16n8k16.row.col.f32.f16.f16.f32 "
                 "{%0,%1,%2,%3}, {%4,%5,%6,%7}, {%8,%9}, {%0,%1,%2,%3};"
                 : "+f"(c[0]), "+f"(c[1]), "+f"(c[2]), "+f"(c[3])
                 : "r"(a[0]), "r"(a[1]), "r"(a[2]), "r"(a[3]), "r"(b0), "r"(b1));
}

__device__ __forceinline__ float sigf(float p) { return 1.0f / (1.0f + expf(-p)); }

__device__ __forceinline__ void store2split(__half* ph, __half* pl, float a, float b) {
    __half2 h;
    h.x = __float2half(a); h.y = __float2half(b);
    __half2 l;
    l.x = __float2half(a - __half2float(h.x));
    l.y = __float2half(b - __half2float(h.y));
    *(__half2*)ph = h;
    *(__half2*)pl = l;
}

__device__ __forceinline__ void store4split(__half* ph, __half* pl, float4 v) {
    __align__(8) __half h[4], l[4];
    float vv[4] = {v.x, v.y, v.z, v.w};
#pragma unroll
    for (int i = 0; i < 4; i++) {
        h[i] = __float2half(vv[i]);
        l[i] = __float2half(vv[i] - __half2float(h[i]));
    }
    *(uint2*)ph = *(uint2*)h;
    *(uint2*)pl = *(uint2*)l;
}

// ------------------ prep: transpose + hi/lo split of weights ----------------
__global__ void prep_transpose(const float* __restrict__ W,
                               __half* __restrict__ Thi,
                               __half* __restrict__ Tlo,
                               int Krows, int Ncols)
{
    __shared__ float t[32][33];
    const float* Wz = W + (size_t)blockIdx.z * Krows * Ncols;
    __half* Hz = Thi + (size_t)blockIdx.z * Ncols * Krows;
    __half* Lz = Tlo + (size_t)blockIdx.z * Ncols * Krows;
    int n0 = blockIdx.x * 32, k0 = blockIdx.y * 32;
    int tx = threadIdx.x, ty = threadIdx.y;
#pragma unroll
    for (int i = 0; i < 4; i++)
        t[ty + 8 * i][tx] = Wz[(size_t)(k0 + ty + 8 * i) * Ncols + n0 + tx];
    __syncthreads();
#pragma unroll
    for (int i = 0; i < 4; i++) {
        int n = n0 + ty + 8 * i;
        float v = t[tx][ty + 8 * i];
        __half h = __float2half(v);
        Hz[(size_t)n * Krows + k0 + tx] = h;
        Lz[(size_t)n * Krows + k0 + tx] = __float2half(v - __half2float(h));
    }
}

// ---------------- layer 0: fused input GEMV + activation -------------------
__global__ void layer0_kernel(const float* __restrict__ x,
                              const float* __restrict__ W0,
                              const float* __restrict__ b0,
                              __half* __restrict__ Ph, __half* __restrict__ Pl,
                              __half* __restrict__ Th, __half* __restrict__ Tl,
                              int B)
{
    int idx = blockIdx.x * blockDim.x + threadIdx.x;
    if (idx >= B * 256) return;
    int b = idx >> 8;
    int c = (idx & 255) * 4;
    float x0 = __ldg(x + b * 4 + 0), x1 = __ldg(x + b * 4 + 1);
    float x2 = __ldg(x + b * 4 + 2), x3 = __ldg(x + b * 4 + 3);
    float4 w0 = *(const float4*)(W0 + c);
    float4 w1 = *(const float4*)(W0 + 1024 + c);
    float4 w2 = *(const float4*)(W0 + 2048 + c);
    float4 w3 = *(const float4*)(W0 + 3072 + c);
    float4 bb = *(const float4*)(b0 + c);
    float p[4], act[4], d[4];
    float wv[4][4] = {{w0.x, w1.x, w2.x, w3.x}, {w0.y, w1.y, w2.y, w3.y},
                      {w0.z, w1.z, w2.z, w3.z}, {w0.w, w1.w, w2.w, w3.w}};
    float bv[4] = {bb.x, bb.y, bb.z, bb.w};
#pragma unroll
    for (int i = 0; i < 4; i++) {
        p[i] = fmaf(x0, wv[i][0], fmaf(x1, wv[i][1], fmaf(x2, wv[i][2], fmaf(x3, wv[i][3], bv[i]))));
        float sg = sigf(p[i]);
        act[i] = p[i] * sg;
        d[i] = sg * fmaf(p[i], 1.0f - sg, 1.0f);
    }
    size_t pb = (size_t)b * DM + c;
    store4split(Ph + pb, Pl + pb, make_float4(act[0], act[1], act[2], act[3]));
#pragma unroll
    for (int j = 0; j < 4; j++) {
        float4 t = make_float4(d[0] * wv[0][j], d[1] * wv[1][j], d[2] * wv[2][j], d[3] * wv[3][j]);
        size_t tb = ((size_t)j * B + b) * DM + c;
        store4split(Th + tb, Tl + tb, t);
    }
}

// ---------------- HMMA GEMM (R6 core) + element-local fused epilogue -------
// modes: 0 primal-hidden (bias+silu, write act + D)
//        1 tangent-hidden (scale by D, write act)
//        2 primal-out (bias, fp32 store)   3 tangent-out (fp32 store)
#define STG 49152
#define NSTAGE 2

__device__ __forceinline__ void load_stage(uint32_t sb,
    const __half* Ah, const __half* Al, const __half* Bh, const __half* Bl,
    int row0, int col0, int k0, int K, int tid)
{
    const __half* gs[4] = {Ah, Al, Bh, Bl};
    const uint32_t po[4] = {0u, 16384u, 32768u, 40960u};
#pragma unroll
    for (int pl = 0; pl < 4; pl++) {
        const __half* g = gs[pl];
        int r0 = (pl < 2) ? row0 : col0;
        int iters = (pl < 2) ? 4 : 2;
        uint32_t pb = sb + po[pl];
#pragma unroll
        for (int it = 0; it < 4; it++) {
            if (it >= iters) break;
            int t = tid + it * 256;
            int r = t >> 3, cc = t & 7;
            cp16(pb + SWZ(r * 128 + cc * 16), g + (size_t)(r0 + r) * K + k0 + cc * 8);
        }
    }
    asm volatile("cp.async.commit_group;" ::: "memory");
}

__global__ void __launch_bounds__(256, 2)
gemm_fused(const __half* __restrict__ Ain, const __half* __restrict__ Alin,
           const __half* __restrict__ Bh, const __half* __restrict__ Bl,
           const float* __restrict__ bias,
           __half* __restrict__ Oh, __half* __restrict__ Ol,
           float* __restrict__ Dbuf, float* __restrict__ C,
           int K, int ldc, int Nstore, int Bn, int mode)
{
    extern __shared__ char smem[];
    uint32_t sbase = smem_u32(smem);
    int tid = threadIdx.x, wid = tid >> 5, lid = tid & 31;
    int wm = wid & 3, wn = wid >> 2;
    int row0 = blockIdx.y * 128;
    int col0 = blockIdx.x * 64;

    float acc[2][4][4];
#pragma unroll
    for (int i = 0; i < 2; i++)
#pragma unroll
        for (int j = 0; j < 4; j++)
#pragma unroll
            for (int q = 0; q < 4; q++) acc[i][j][q] = 0.0f;

    const int KITER = K >> 6;
    load_stage(sbase + 0 * STG, Ain, Alin, Bh, Bl, row0, col0, 0, K, tid);
    load_stage(sbase + 1 * STG, Ain, Alin, Bh, Bl, row0, col0, 64, K, tid);

    int lrow = lid & 15;
    int kadd = (lid & 16) ? 8 : 0;

    for (int i = 0; i < KITER; i++) {
        asm volatile("cp.async.wait_group 1;" ::: "memory");
        __syncthreads();
        uint32_t stg = sbase + (i & 1) * STG;
        uint32_t Abh = stg, Abl = stg + 16384, Bbh = stg + 32768, Bbl = stg + 40960;

#pragma unroll
        for (int ks = 0; ks < 4; ks++) {
            int col = ks * 16 + kadd;
            uint32_t ahi[2][4], alo[2][4], bhi[2][4], blo[2][4];
#pragma unroll
            for (int mi = 0; mi < 2; mi++) {
                uint32_t off = SWZ((wm * 32 + mi * 16 + lrow) * 128 + col * 2);
                ldsm4(ahi[mi], Abh + off);
                ldsm4(alo[mi], Abl + off);
            }
#pragma unroll
            for (int j = 0; j < 2; j++) {
                uint32_t off = SWZ((wn * 32 + j * 16 + lrow) * 128 + col * 2);
                ldsm4(bhi[j], Bbh + off);
                ldsm4(blo[j], Bbl + off);
            }
#pragma unroll
            for (int mi = 0; mi < 2; mi++)
#pragma unroll
                for (int j = 0; j < 2; j++) {
                    mma16816(acc[mi][2 * j],     ahi[mi], bhi[j][0], bhi[j][2]);
                    mma16816(acc[mi][2 * j + 1], ahi[mi], bhi[j][1], bhi[j][3]);
                }
#pragma unroll
            for (int mi = 0; mi < 2; mi++)
#pragma unroll
                for (int j = 0; j < 2; j++) {
                    mma16816(acc[mi][2 * j],     ahi[mi], blo[j][0], blo[j][2]);
                    mma16816(acc[mi][2 * j + 1], ahi[mi], blo[j][1], blo[j][3]);
                }
#pragma unroll
            for (int mi = 0; mi < 2; mi++)
#pragma unroll
                for (int j = 0; j < 2; j++) {
                    mma16816(acc[mi][2 * j],     alo[mi], bhi[j][0], bhi[j][2]);
                    mma16816(acc[mi][2 * j + 1], alo[mi], bhi[j][1], bhi[j][3]);
                }
        }
        __syncthreads();
        if (i + NSTAGE < KITER)
            load_stage(stg, Ain, Alin, Bh, Bl, row0, col0, (i + NSTAGE) * 64, K, tid);
        else
            asm volatile("cp.async.commit_group;" ::: "memory");
    }

    int trow = lid >> 2, tcol = (lid & 3) * 2;
    // tangent modes: base row of this tangent block (tile never straddles j blocks)
    int jB = (mode == 1 || mode == 3) ? (row0 / Bn) * Bn : 0;

#pragma unroll
    for (int mi = 0; mi < 2; mi++) {
#pragma unroll
        for (int j = 0; j < 4; j++) {
            int gc = col0 + wn * 32 + j * 8 + tcol;
#pragma unroll
            for (int hv = 0; hv < 2; hv++) {        // hv=0: row gr0, hv=1: row gr0+8
                int gr = row0 + wm * 32 + mi * 16 + trow + hv * 8;
                float a0 = acc[mi][j][2 * hv], a1 = acc[mi][j][2 * hv + 1];
                if (mode == 0) {
                    float p0 = a0 + bias[gc], p1 = a1 + bias[gc + 1];
                    float s0 = sigf(p0), s1 = sigf(p1);
                    size_t o = (size_t)gr * DM + gc;
                    store2split(Oh + o, Ol + o, p0 * s0, p1 * s1);
                    float2 dd;
                    dd.x = s0 * fmaf(p0, 1.0f - s0, 1.0f);
                    dd.y = s1 * fmaf(p1, 1.0f - s1, 1.0f);
                    *(float2*)(Dbuf + o) = dd;
                } else if (mode == 1) {
                    float2 dd = *(const float2*)(Dbuf + (size_t)(gr - jB) * DM + gc);
                    size_t o = (size_t)gr * DM + gc;
                    store2split(Oh + o, Ol + o, a0 * dd.x, a1 * dd.y);
                } else {
                    if (gc < Nstore) {
                        float2 v = make_float2(a0, a1);
                        if (mode == 2) { v.x += bias[gc]; v.y += bias[gc + 1]; }
                        *(float2*)(C + (size_t)gr * ldc + gc) = v;
                    }
                }
            }
        }
    }
}

// ---------------- head: softmax-mixture derivative, warp per point ---------
__global__ void finalize_kernel(const float* __restrict__ OUTP,
                                const float* __restrict__ OUTT,
                                float* __restrict__ y, int B)
{
    int warp = (blockIdx.x * blockDim.x + threadIdx.x) >> 5;
    int lane = threadIdx.x & 31;
    if (warp >= B) return;
    const float* o = OUTP + (size_t)warp * ODIM;

    float l0 = o[lane], l1 = o[lane + 32];
    float m = fmaxf(l0, l1);
#pragma unroll
    for (int s = 16; s; s >>= 1) m = fmaxf(m, __shfl_xor_sync(0xFFFFFFFFu, m, s));
    float e0 = expf(l0 - m), e1 = expf(l1 - m);
    float S = e0 + e1;
#pragma unroll
    for (int s = 16; s; s >>= 1) S += __shfl_xor_sync(0xFFFFFFFFu, S, s);
    float s0 = e0 / S, s1 = e1 / S;

    float v0[6], v1[6];
#pragma unroll
    for (int t = 0; t < 6; t++) {
        v0[t] = o[64 + 6 * lane + t];
        v1[t] = o[64 + 6 * (lane + 32) + t];
    }

    float Dm[4][6];
#pragma unroll
    for (int j = 0; j < 4; j++) {
        const float* tj = OUTT + ((size_t)j * B + warp) * ODIM;
        float g0 = tj[lane], g1 = tj[lane + 32];
        float dot = s0 * g0 + s1 * g1;
#pragma unroll
        for (int s = 16; s; s >>= 1) dot += __shfl_xor_sync(0xFFFFFFFFu, dot, s);
#pragma unroll
        for (int t = 0; t < 6; t++) {
            float dv0 = tj[64 + 6 * lane + t];
            float dv1 = tj[64 + 6 * (lane + 32) + t];
            float val = s0 * fmaf(g0 - dot, v0[t], dv0) + s1 * fmaf(g1 - dot, v1[t], dv1);
#pragma unroll
            for (int s = 16; s; s >>= 1) val += __shfl_xor_sync(0xFFFFFFFFu, val, s);
            Dm[j][t] = val;
        }
    }
    if (lane == 0) {
        float u0 =  Dm[1][0] + Dm[2][1] + Dm[3][2];
        float u1 = -Dm[0][0] + Dm[2][3] + Dm[3][4];
        float u2 = -Dm[0][1] - Dm[1][3] + Dm[3][5];
        float u3 = -Dm[0][2] - Dm[1][4] - Dm[2][5];
        *(float4*)(y + (size_t)warp * 4) = make_float4(u0 * 10.0f, u1, u2, u3);
    }
}

// ---------------------------------------------------------------------------
extern "C" void kernel_launch(void* const* d_in, const int* in_sizes, int n_in,
                              void* d_out, int out_size)
{
    const float* x    = (const float*)d_in[0];
    const float* W0   = (const float*)d_in[1];
    const float* b0   = (const float*)d_in[2];
    const float* Wh   = (const float*)d_in[3];
    const float* bh   = (const float*)d_in[4];
    const float* Wout = (const float*)d_in[5];
    const float* bout = (const float*)d_in[6];
    float* y = (float*)d_out;

    int B = in_sizes[0] / 4;

    __half *P0h, *P0l, *P1h, *P1l, *T0h, *T0l, *T1h, *T1l, *WThi, *WTlo;
    float *Dbuf, *OUTP, *OUTT;
    cudaGetSymbolAddress((void**)&P0h, g_P0h);
    cudaGetSymbolAddress((void**)&P0l, g_P0l);
    cudaGetSymbolAddress((void**)&P1h, g_P1h);
    cudaGetSymbolAddress((void**)&P1l, g_P1l);
    cudaGetSymbolAddress((void**)&T0h, g_T0h);
    cudaGetSymbolAddress((void**)&T0l, g_T0l);
    cudaGetSymbolAddress((void**)&T1h, g_T1h);
    cudaGetSymbolAddress((void**)&T1l, g_T1l);
    cudaGetSymbolAddress((void**)&Dbuf, g_D);
    cudaGetSymbolAddress((void**)&OUTP, g_OUTP);
    cudaGetSymbolAddress((void**)&OUTT, g_OUTT);
    cudaGetSymbolAddress((void**)&WThi, g_WThi);
    cudaGetSymbolAddress((void**)&WTlo, g_WTlo);

    static int smem_set = 0;
    if (!smem_set) {
        cudaFuncSetAttribute(gemm_fused, cudaFuncAttributeMaxDynamicSharedMemorySize,
                             NSTAGE * STG);
        smem_set = 1;
    }

    prep_transpose<<<dim3(32, 32, NLAY), dim3(32, 8)>>>(Wh, WThi, WTlo, DM, DM);
    prep_transpose<<<dim3(ODIM / 32, 32, 1), dim3(32, 8)>>>(
        Wout, WThi + (size_t)NLAY * DM * DM, WTlo + (size_t)NLAY * DM * DM, DM, ODIM);

    layer0_kernel<<<(B * 256 + 255) / 256, 256>>>(x, W0, b0, P0h, P0l, T0h, T0l, B);

    __half *pch = P0h, *pcl = P0l, *pnh = P1h, *pnl = P1l;
    __half *tch = T0h, *tcl = T0l, *tnh = T1h, *tnl = T1l;

    dim3 gP(DM / 64, B / 128);
    dim3 gT(DM / 64, (4 * B) / 128);
    for (int l = 0; l < NLAY; l++) {
        const __half* wh = WThi + (size_t)l * DM * DM;
        const __half* wl = WTlo + (size_t)l * DM * DM;
        // primal: act + D
        gemm_fused<<<gP, 256, NSTAGE * STG>>>(pch, pcl, wh, wl,
            bh + (size_t)l * DM, pnh, pnl, Dbuf, nullptr, DM, 0, 0, B, 0);
        // tangent: scale by D
        gemm_fused<<<gT, 256, NSTAGE * STG>>>(tch, tcl, wh, wl,
            nullptr, tnh, tnl, Dbuf, nullptr, DM, 0, 0, B, 1);
        __half* t;
        t = pch; pch = pnh; pnh = t;  t = pcl; pcl = pnl; pnl = t;
        t = tch; tch = tnh; tnh = t;  t = tcl; tcl = tnl; tnl = t;
    }

    const __half* woh = WThi + (size_t)NLAY * DM * DM;
    const __half* wol = WTlo + (size_t)NLAY * DM * DM;
    dim3 gPo(512 / 64, B / 128);
    dim3 gTo(512 / 64, (4 * B) / 128);
    gemm_fused<<<gPo, 256, NSTAGE * STG>>>(pch, pcl, woh, wol,
        bout, nullptr, nullptr, nullptr, OUTP, DM, ODIM, ODIM, B, 2);
    gemm_fused<<<gTo, 256, NSTAGE * STG>>>(tch, tcl, woh, wol,
        nullptr, nullptr, nullptr, nullptr, OUTT, DM, ODIM, ODIM, B, 3);

    finalize_kernel<<<(B * 32 + 255) / 256, 256>>>(OUTP, OUTT, y, B);
}